// round 10
// baseline (speedup 1.0000x reference)
#include <cuda_runtime.h>
#include <cuda_fp16.h>

#define D 64
#define NMAX 50048
#define EMAX 800000

typedef unsigned long long ull;

// ---------------- scratch (no allocation allowed) ----------------
__device__ int    g_degi[NMAX];
__device__ int    g_cursor[NMAX];
__device__ float  g_dinv[NMAX];
__device__ int    g_rowptr[NMAX + 1];
__device__ ull    g_state[64];           // lookback scan state (value<<2 | status)
__device__ int2   g_edge[EMAX + 8];      // {src, wn bits}; padded
__device__ __half g_x16[(size_t)NMAX * D];
__device__ __half g_hA16[(size_t)NMAX * D];
__device__ __half g_hB16[(size_t)NMAX * D];
__device__ __half g_y16[(size_t)NMAX * D];
__device__ float  g_acc[(size_t)NMAX * D];
__device__ __half g_whi[8 * 4096];       // W hi fp16 planes (8 matrices)
__device__ __half g_wlo[8 * 4096];       // W lo fp16 planes

// ---------------- degree count (also resets scan state) ----------------
__global__ void k_deg(const int* __restrict__ dst, int E) {
    int e = blockIdx.x * blockDim.x + threadIdx.x;
    if (blockIdx.x == 0 && threadIdx.x < 64) g_state[threadIdx.x] = 0ull;
    if (e < E) atomicAdd(&g_degi[dst[e]], 1);
}

// ---------------- single-pass decoupled-lookback scan + dinv + cursor ----
__global__ void __launch_bounds__(1024) k_scan(int n) {
    const int tid = threadIdx.x;
    const int lane = tid & 31;
    const int w = tid >> 5;
    const int i = blockIdx.x * 1024 + tid;
    int v = (i < n) ? g_degi[i] : 0;

    int s = v;
#pragma unroll
    for (int off = 1; off < 32; off <<= 1) {
        int t = __shfl_up_sync(0xffffffffu, s, off);
        if (lane >= off) s += t;
    }
    __shared__ int wsum[32];
    if (lane == 31) wsum[w] = s;
    __syncthreads();
    if (w == 0) {
        int t = wsum[lane];
#pragma unroll
        for (int off = 1; off < 32; off <<= 1) {
            int u = __shfl_up_sync(0xffffffffu, t, off);
            if (lane >= off) t += u;
        }
        wsum[lane] = t;
    }
    __syncthreads();
    const int incl = s + (w > 0 ? wsum[w - 1] : 0);
    const int total = wsum[31];

    __shared__ int base_sh;
    if (tid == 0) {
        if (blockIdx.x == 0) {
            atomicExch(&g_state[0], ((ull)(unsigned)total << 2) | 2ull);
            base_sh = 0;
        } else {
            atomicExch(&g_state[blockIdx.x], ((ull)(unsigned)total << 2) | 1ull);
            int base = 0;
            for (int b = blockIdx.x - 1; b >= 0; b--) {
                ull st;
                do { st = atomicAdd(&g_state[b], 0ull); } while ((st & 3ull) == 0ull);
                base += (int)(unsigned)(st >> 2);
                if ((st & 3ull) == 2ull) break;
            }
            atomicExch(&g_state[blockIdx.x], ((ull)(unsigned)(base + total) << 2) | 2ull);
            base_sh = base;
        }
    }
    __syncthreads();
    const int base = base_sh;

    if (i < n) {
        int di = g_degi[i];
        int inclusive = base + incl;
        int excl = inclusive - di;
        g_rowptr[i] = excl;
        g_cursor[i] = excl;
        g_dinv[i] = (di > 0) ? rsqrtf((float)di) : 0.0f;
        if (i == n - 1) g_rowptr[n] = inclusive;
    }
}

// ---- fill CSR + quantize x + split W + init out (block-range split) ----
__global__ void k_fillquant(const int* __restrict__ src, const int* __restrict__ dst,
                            const float* __restrict__ x, __half* __restrict__ x16,
                            const float* __restrict__ W0, const float* __restrict__ W1,
                            const float* __restrict__ bout, float* __restrict__ out,
                            int E, int n4, int G, int EB, int QB) {
    if ((int)blockIdx.x < EB) {
        int e = blockIdx.x * 256 + threadIdx.x;
        if (e >= E) return;
        int s = src[e], d = dst[e];
        int pos = atomicAdd(&g_cursor[d], 1);
        int2 ed;
        ed.x = s;
        ed.y = __float_as_int(g_dinv[s] * g_dinv[d]);
        g_edge[pos] = ed;
    } else if ((int)blockIdx.x < EB + QB) {
        int i = (blockIdx.x - EB) * 256 + threadIdx.x;
        if (i >= n4) return;
        float4 v = ((const float4*)x)[i];
        __half2 a = __floats2half2_rn(v.x, v.y);
        __half2 b = __floats2half2_rn(v.z, v.w);
        uint2 p;
        p.x = *(unsigned*)&a;
        p.y = *(unsigned*)&b;
        ((uint2*)x16)[i] = p;
    } else if ((int)blockIdx.x == gridDim.x - 1) {
        int i = threadIdx.x;
        if (i < G) out[i] = bout[0];
    } else {
        int c = (blockIdx.x - EB - QB) * 256 + threadIdx.x;
        if (c >= 8192) return;
        int f = c * 4;
        float4 wv = (f < 16384) ? *(const float4*)&W0[f] : *(const float4*)&W1[f - 16384];
        __half hx = __float2half_rn(wv.x), hy = __float2half_rn(wv.y);
        __half hz = __float2half_rn(wv.z), hw = __float2half_rn(wv.w);
        __half lx = __float2half_rn(wv.x - __half2float(hx));
        __half ly = __float2half_rn(wv.y - __half2float(hy));
        __half lz = __float2half_rn(wv.z - __half2float(hz));
        __half lw = __float2half_rn(wv.w - __half2float(hw));
        __half2 h01 = __halves2half2(hx, hy), h23 = __halves2half2(hz, hw);
        __half2 l01 = __halves2half2(lx, ly), l23 = __halves2half2(lz, lw);
        uint2 ph, pl;
        ph.x = *(unsigned*)&h01;  ph.y = *(unsigned*)&h23;
        pl.x = *(unsigned*)&l01;  pl.y = *(unsigned*)&l23;
        *(uint2*)&g_whi[f] = ph;
        *(uint2*)&g_wlo[f] = pl;
    }
}

// ---------------- ldmatrix / mma helpers ----------------
#define LDSM_X4(r0, r1, r2, r3, a) \
    asm volatile("ldmatrix.sync.aligned.m8n8.x4.shared.b16 {%0,%1,%2,%3}, [%4];" \
                 : "=r"(r0), "=r"(r1), "=r"(r2), "=r"(r3) : "r"(a))
#define LDSM_X4_T(r0, r1, r2, r3, a) \
    asm volatile("ldmatrix.sync.aligned.m8n8.x4.trans.shared.b16 {%0,%1,%2,%3}, [%4];" \
                 : "=r"(r0), "=r"(r1), "=r"(r2), "=r"(r3) : "r"(a))
#define HMMA(d0, d1, d2, d3, a0, a1, a2, a3, b0, b1) \
    asm volatile("mma.sync.aligned.m16n8k16.row.col.f32.f16.f16.f32 " \
                 "{%0,%1,%2,%3}, {%4,%5,%6,%7}, {%8,%9}, {%0,%1,%2,%3};" \
                 : "+f"(d0), "+f"(d1), "+f"(d2), "+f"(d3) \
                 : "r"(a0), "r"(a1), "r"(a2), "r"(a3), "r"(b0), "r"(b1))

#define HS_STRIDE 72

#define GEMM_PASS() \
    do { \
        unsigned aAddr = (unsigned)__cvta_generic_to_shared(&Hs[(m0 + lr) * HS_STRIDE + lc]); \
        unsigned bh0 = (unsigned)__cvta_generic_to_shared(&Whi[lr * HS_STRIDE + n0w + lc]); \
        unsigned bh1 = (unsigned)__cvta_generic_to_shared(&Whi[lr * HS_STRIDE + n0w + 16 + lc]); \
        unsigned bl0 = (unsigned)__cvta_generic_to_shared(&Wlo[lr * HS_STRIDE + n0w + lc]); \
        unsigned bl1 = (unsigned)__cvta_generic_to_shared(&Wlo[lr * HS_STRIDE + n0w + 16 + lc]); \
        _Pragma("unroll") \
        for (int ks = 0; ks < 4; ks++) { \
            unsigned a0, a1, a2, a3; \
            LDSM_X4(a0, a1, a2, a3, aAddr + ks * 32); \
            unsigned h0, h1, h2, h3, h4, h5, h6, h7; \
            LDSM_X4_T(h0, h1, h2, h3, bh0 + ks * kstepB); \
            LDSM_X4_T(h4, h5, h6, h7, bh1 + ks * kstepB); \
            unsigned l0, l1, l2, l3, l4, l5, l6, l7; \
            LDSM_X4_T(l0, l1, l2, l3, bl0 + ks * kstepB); \
            LDSM_X4_T(l4, l5, l6, l7, bl1 + ks * kstepB); \
            HMMA(d0[0], d1[0], d2[0], d3[0], a0, a1, a2, a3, h0, h1); \
            HMMA(d0[1], d1[1], d2[1], d3[1], a0, a1, a2, a3, h2, h3); \
            HMMA(d0[2], d1[2], d2[2], d3[2], a0, a1, a2, a3, h4, h5); \
            HMMA(d0[3], d1[3], d2[3], d3[3], a0, a1, a2, a3, h6, h7); \
            HMMA(d0[0], d1[0], d2[0], d3[0], a0, a1, a2, a3, l0, l1); \
            HMMA(d0[1], d1[1], d2[1], d3[1], a0, a1, a2, a3, l2, l3); \
            HMMA(d0[2], d1[2], d2[2], d3[2], a0, a1, a2, a3, l4, l5); \
            HMMA(d0[3], d1[3], d2[3], d3[3], a0, a1, a2, a3, l6, l7); \
        } \
    } while (0)

// per-edge FMA on a prefetched int4 pair (4 edges)
#define HOP4(M0, M1)                                                          \
    do {                                                                      \
        float2 v0 = __half22float2(__ldg(hbase + (size_t)(M0).x * 32));       \
        float2 v1 = __half22float2(__ldg(hbase + (size_t)(M0).z * 32));       \
        float2 v2 = __half22float2(__ldg(hbase + (size_t)(M1).x * 32));       \
        float2 v3 = __half22float2(__ldg(hbase + (size_t)(M1).z * 32));       \
        float w0 = __int_as_float((M0).y), w1 = __int_as_float((M0).w);       \
        float w2 = __int_as_float((M1).y), w3 = __int_as_float((M1).w);       \
        ax += w0 * v0.x;  ay += w0 * v0.y;                                    \
        ax += w1 * v1.x;  ay += w1 * v1.y;                                    \
        ax += w2 * v2.x;  ay += w2 * v2.y;                                    \
        ax += w3 * v3.x;  ay += w3 * v3.y;                                    \
    } while (0)

// ---------------- stage kernel: HMMA GEMM blocks + hop blocks ----------
// GMODE 0: acc = h@W + bias        GMODE 1: acc += h@W
// GMODE 2: y16 = prelu(acc + h@W); if FUSE: acc = y@Wn + bias2 (layer fuse)
// GMODE 3: pool(prelu(acc + h@W)) -> out
template <int GMODE, bool HOP, bool FUSE>
__global__ void __launch_bounds__(256, 7) k_stage(const __half* __restrict__ hin,
                                                  const __half* __restrict__ whi,
                                                  const __half* __restrict__ wlo,
                                                  const __half* __restrict__ wnh,
                                                  const __half* __restrict__ wnl,
                                                  float* __restrict__ acc,
                                                  const float* __restrict__ bias,
                                                  const float* __restrict__ bias2,
                                                  const float* __restrict__ alpha,
                                                  __half* __restrict__ hopout,
                                                  __half* __restrict__ y16,
                                                  const int* __restrict__ bids,
                                                  const float* __restrict__ Wout,
                                                  float* __restrict__ out,
                                                  int N, int GB) {
    __shared__ __half Hs[64 * HS_STRIDE];
    __shared__ __half Whi[64 * HS_STRIDE];
    __shared__ __half Wlo[64 * HS_STRIDE];

    const int tid = threadIdx.x;

    if (HOP && (int)blockIdx.x >= GB) {
        const int lane = tid & 31;
        const int node = (blockIdx.x - GB) * 8 + (tid >> 5);
        if (node >= N) return;
        int p = g_rowptr[node];
        const int end = g_rowptr[node + 1];
        const __half2* __restrict__ hbase = (const __half2*)hin + lane;
        float ax = 0.f, ay = 0.f;
        if (p < end && (p & 1)) {  // scalar head to even alignment
            int2 e = g_edge[p];
            float wv = __int_as_float(e.y);
            float2 v = __half22float2(__ldg(hbase + (size_t)e.x * 32));
            ax += wv * v.x;  ay += wv * v.y;
            p++;
        }
        if (p + 4 <= end) {
            // software-pipelined 4-edge batches: prefetch next metadata
            int4 m0 = *(const int4*)&g_edge[p];
            int4 m1 = *(const int4*)&g_edge[p + 2];
            for (; p + 8 <= end; p += 4) {
                int4 n0 = *(const int4*)&g_edge[p + 4];
                int4 n1 = *(const int4*)&g_edge[p + 6];
                HOP4(m0, m1);
                m0 = n0;  m1 = n1;
            }
            HOP4(m0, m1);
            p += 4;
        }
        for (; p < end; p++) {  // tail 0-3 edges
            int2 e = g_edge[p];
            float wv = __int_as_float(e.y);
            float2 v = __half22float2(__ldg(hbase + (size_t)e.x * 32));
            ax += wv * v.x;  ay += wv * v.y;
        }
        *(__half2*)&hopout[(size_t)node * D + lane * 2] = __floats2half2_rn(ax, ay);
        return;
    }

    // ================= HMMA GEMM block =================
    const int n0blk = blockIdx.x * 64;

#pragma unroll
    for (int i = 0; i < 2; i++) {
        int idx = tid + i * 256;
        int r = idx >> 3;
        int c8 = (idx & 7) * 8;
        int4 v = make_int4(0, 0, 0, 0);
        if (n0blk + r < N) v = *(const int4*)&hin[(size_t)(n0blk + r) * D + c8];
        *(int4*)&Hs[r * HS_STRIDE + c8] = v;
        *(int4*)&Whi[r * HS_STRIDE + c8] = *(const int4*)&whi[r * 64 + c8];
        *(int4*)&Wlo[r * HS_STRIDE + c8] = *(const int4*)&wlo[r * 64 + c8];
    }
    __syncthreads();

    const int w = tid >> 5;
    const int lane = tid & 31;
    const int m0 = (w & 3) * 16;
    const int n0w = (w >> 2) * 32;
    const int lr = lane & 15;
    const int lc = (lane >> 4) * 8;
    const unsigned kstepB = 16 * HS_STRIDE * 2;

    float d0[4], d1[4], d2[4], d3[4];
#pragma unroll
    for (int j = 0; j < 4; j++) { d0[j] = d1[j] = d2[j] = d3[j] = 0.f; }

    GEMM_PASS();

    // ---- epilogue ----
    const int grp = lane >> 2;
    const int qt = lane & 3;
    const int row0 = n0blk + m0 + grp;
    const int row1 = row0 + 8;
    const int rl0 = m0 + grp;
    const int rl1 = rl0 + 8;
    float a0s = 0.f;
    if (GMODE >= 2) a0s = alpha[0];
    float part0 = 0.f, part1 = 0.f;

    if (GMODE == 2 && FUSE) __syncthreads();

#pragma unroll
    for (int j = 0; j < 4; j++) {
        const int cb = n0w + j * 8 + qt * 2;
        float2 bvj = make_float2(0.f, 0.f);
        if (GMODE == 0) bvj = *(const float2*)&bias[cb];
        float2 wvj = make_float2(0.f, 0.f);
        if (GMODE == 3) wvj = *(const float2*)&Wout[cb];

        if (GMODE == 0) {
            if (row0 < N)
                *(float2*)&acc[(size_t)row0 * D + cb] = make_float2(d0[j] + bvj.x, d1[j] + bvj.y);
            if (row1 < N)
                *(float2*)&acc[(size_t)row1 * D + cb] = make_float2(d2[j] + bvj.x, d3[j] + bvj.y);
        } else if (GMODE == 1) {
            if (row0 < N) {
                float* ap = &acc[(size_t)row0 * D + cb];
                float2 o = *(const float2*)ap;
                o.x += d0[j]; o.y += d1[j];
                *(float2*)ap = o;
            }
            if (row1 < N) {
                float* ap = &acc[(size_t)row1 * D + cb];
                float2 o = *(const float2*)ap;
                o.x += d2[j]; o.y += d3[j];
                *(float2*)ap = o;
            }
        } else {
            float2 o0 = make_float2(0.f, 0.f), o1 = make_float2(0.f, 0.f);
            if (row0 < N) {
                o0 = *(const float2*)&acc[(size_t)row0 * D + cb];
                o0.x += d0[j]; o0.y += d1[j];
                o0.x = (o0.x >= 0.f) ? o0.x : a0s * o0.x;
                o0.y = (o0.y >= 0.f) ? o0.y : a0s * o0.y;
            }
            if (row1 < N) {
                o1 = *(const float2*)&acc[(size_t)row1 * D + cb];
                o1.x += d2[j]; o1.y += d3[j];
                o1.x = (o1.x >= 0.f) ? o1.x : a0s * o1.x;
                o1.y = (o1.y >= 0.f) ? o1.y : a0s * o1.y;
            }
            if (GMODE == 2) {
                __half2 h0 = __floats2half2_rn(o0.x, o0.y);
                __half2 h1 = __floats2half2_rn(o1.x, o1.y);
                if (row0 < N) *(__half2*)&y16[(size_t)row0 * D + cb] = h0;
                if (row1 < N) *(__half2*)&y16[(size_t)row1 * D + cb] = h1;
                if (FUSE) {
                    *(__half2*)&Hs[rl0 * HS_STRIDE + cb] = h0;
                    *(__half2*)&Hs[rl1 * HS_STRIDE + cb] = h1;
                }
            } else {
                if (row0 < N) part0 += o0.x * wvj.x + o0.y * wvj.y;
                if (row1 < N) part1 += o1.x * wvj.x + o1.y * wvj.y;
            }
        }
    }

    if (GMODE == 3) {
        part0 += __shfl_xor_sync(0xffffffffu, part0, 1);
        part0 += __shfl_xor_sync(0xffffffffu, part0, 2);
        part1 += __shfl_xor_sync(0xffffffffu, part1, 1);
        part1 += __shfl_xor_sync(0xffffffffu, part1, 2);
        if (qt == 0) {
            if (row0 < N) atomicAdd(&out[bids[row0]], part0);
            if (row1 < N) atomicAdd(&out[bids[row1]], part1);
        }
    }

    if (GMODE == 2 && FUSE) {
        __syncthreads();
#pragma unroll
        for (int i = 0; i < 2; i++) {
            int idx = tid + i * 256;
            int r = idx >> 3;
            int c8 = (idx & 7) * 8;
            *(int4*)&Whi[r * HS_STRIDE + c8] = *(const int4*)&wnh[r * 64 + c8];
            *(int4*)&Wlo[r * HS_STRIDE + c8] = *(const int4*)&wnl[r * 64 + c8];
        }
        __syncthreads();
#pragma unroll
        for (int j = 0; j < 4; j++) { d0[j] = d1[j] = d2[j] = d3[j] = 0.f; }
        GEMM_PASS();
#pragma unroll
        for (int j = 0; j < 4; j++) {
            const int cb = n0w + j * 8 + qt * 2;
            float2 b2 = *(const float2*)&bias2[cb];
            if (row0 < N)
                *(float2*)&acc[(size_t)row0 * D + cb] = make_float2(d0[j] + b2.x, d1[j] + b2.y);
            if (row1 < N)
                *(float2*)&acc[(size_t)row1 * D + cb] = make_float2(d2[j] + b2.x, d3[j] + b2.y);
        }
    }
}

// ---------------- launch ----------------
extern "C" void kernel_launch(void* const* d_in, const int* in_sizes, int n_in,
                              void* d_out, int out_size) {
    const float* x    = (const float*)d_in[0];
    const int*   ei   = (const int*)d_in[1];
    const int*   bids = (const int*)d_in[2];
    const float* W0   = (const float*)d_in[3];
    const float* b0   = (const float*)d_in[4];
    const float* W1   = (const float*)d_in[5];
    const float* b1   = (const float*)d_in[6];
    const float* al0  = (const float*)d_in[7];
    const float* al1  = (const float*)d_in[8];
    const float* Wout = (const float*)d_in[9];
    const float* bout = (const float*)d_in[10];
    float* out = (float*)d_out;

    const int N = in_sizes[0] / D;
    const int E = in_sizes[1] / 2;
    const int* src = ei;
    const int* dst = ei + E;

    void* p_degi;
    __half *x16, *hA, *hB, *y16, *whi, *wlo;
    float* accp;
    cudaGetSymbolAddress(&p_degi, g_degi);
    cudaGetSymbolAddress((void**)&x16, g_x16);
    cudaGetSymbolAddress((void**)&hA, g_hA16);
    cudaGetSymbolAddress((void**)&hB, g_hB16);
    cudaGetSymbolAddress((void**)&y16, g_y16);
    cudaGetSymbolAddress((void**)&whi, g_whi);
    cudaGetSymbolAddress((void**)&wlo, g_wlo);
    cudaGetSymbolAddress((void**)&accp, g_acc);

    cudaMemsetAsync(p_degi, 0, (size_t)N * sizeof(int));

    const int EB = (E + 255) / 256;
    const int QB = (N * 16 + 255) / 256;
    const int WB = 32;
    k_deg<<<EB, 256>>>(dst, E);
    k_scan<<<(N + 1023) / 1024, 1024>>>(N);
    k_fillquant<<<EB + QB + WB + 1, 256>>>(src, dst, x, x16, W0, W1, bout, out,
                                           E, N * 16, out_size, EB, QB);

    const int GB = (N + 63) / 64;
    const int HB = (N + 7) / 8;
    const int FULL = GB + HB;

    // ---- layer 0 ----
    k_stage<0, true , false><<<FULL, 256>>>(x16, whi,         wlo,         nullptr, nullptr, accp, b0,      nullptr, nullptr, hA,  nullptr, nullptr, nullptr, nullptr, N, GB);
    k_stage<1, true , false><<<FULL, 256>>>(hA,  whi + 4096,  wlo + 4096,  nullptr, nullptr, accp, nullptr, nullptr, nullptr, hB,  nullptr, nullptr, nullptr, nullptr, N, GB);
    k_stage<1, true , false><<<FULL, 256>>>(hB,  whi + 8192,  wlo + 8192,  nullptr, nullptr, accp, nullptr, nullptr, nullptr, hA,  nullptr, nullptr, nullptr, nullptr, N, GB);
    // layer boundary: y = prelu(acc + hA@W0_3); acc = y@W1_0 + b1 (fused)
    k_stage<2, false, true ><<<GB,   256>>>(hA,  whi + 12288, wlo + 12288, whi + 16384, wlo + 16384, accp, nullptr, b1, al0, nullptr, y16, nullptr, nullptr, nullptr, N, GB);

    // ---- layer 1 ----
    k_stage<1, true , false><<<HB,   256>>>(y16, whi,         wlo,         nullptr, nullptr, accp, nullptr, nullptr, nullptr, hB,  nullptr, nullptr, nullptr, nullptr, N, 0);
    k_stage<1, true , false><<<FULL, 256>>>(hB,  whi + 20480, wlo + 20480, nullptr, nullptr, accp, nullptr, nullptr, nullptr, hA,  nullptr, nullptr, nullptr, nullptr, N, GB);
    k_stage<1, true , false><<<FULL, 256>>>(hA,  whi + 24576, wlo + 24576, nullptr, nullptr, accp, nullptr, nullptr, nullptr, hB,  nullptr, nullptr, nullptr, nullptr, N, GB);
    k_stage<3, false, false><<<GB,   256>>>(hB,  whi + 28672, wlo + 28672, nullptr, nullptr, accp, nullptr, nullptr, al1,     nullptr, nullptr, bids, Wout, out, N, GB);
}

// round 11
// speedup vs baseline: 1.0497x; 1.0497x over previous
#include <cuda_runtime.h>
#include <cuda_fp16.h>

#define D 64
#define NMAX 50048
#define EMAX 800000

typedef unsigned long long ull;

// ---------------- scratch (no allocation allowed) ----------------
__device__ int    g_degi[NMAX];
__device__ int    g_cursor[NMAX];
__device__ float  g_dinv[NMAX];
__device__ int    g_rowptr[NMAX + 1];
__device__ ull    g_state[64];           // lookback scan state (value<<2 | status)
__device__ int2   g_edge[EMAX + 8];      // {src, wn bits}; padded
__device__ __half g_x16[(size_t)NMAX * D];
__device__ __half g_hA16[(size_t)NMAX * D];
__device__ __half g_hB16[(size_t)NMAX * D];
__device__ __half g_y16[(size_t)NMAX * D];
__device__ float  g_acc[(size_t)NMAX * D];
__device__ __half g_whi[8 * 4096];       // W hi fp16 planes (8 matrices)
__device__ __half g_wlo[8 * 4096];       // W lo fp16 planes

// ---------------- degree count (also resets scan state) ----------------
__global__ void k_deg(const int* __restrict__ dst, int E) {
    int e = blockIdx.x * blockDim.x + threadIdx.x;
    if (blockIdx.x == 0 && threadIdx.x < 64) g_state[threadIdx.x] = 0ull;
    if (e < E) atomicAdd(&g_degi[dst[e]], 1);
}

// ---------------- single-pass decoupled-lookback scan + dinv + cursor ----
__global__ void __launch_bounds__(1024) k_scan(int n) {
    const int tid = threadIdx.x;
    const int lane = tid & 31;
    const int w = tid >> 5;
    const int i = blockIdx.x * 1024 + tid;
    int v = (i < n) ? g_degi[i] : 0;

    int s = v;
#pragma unroll
    for (int off = 1; off < 32; off <<= 1) {
        int t = __shfl_up_sync(0xffffffffu, s, off);
        if (lane >= off) s += t;
    }
    __shared__ int wsum[32];
    if (lane == 31) wsum[w] = s;
    __syncthreads();
    if (w == 0) {
        int t = wsum[lane];
#pragma unroll
        for (int off = 1; off < 32; off <<= 1) {
            int u = __shfl_up_sync(0xffffffffu, t, off);
            if (lane >= off) t += u;
        }
        wsum[lane] = t;
    }
    __syncthreads();
    const int incl = s + (w > 0 ? wsum[w - 1] : 0);
    const int total = wsum[31];

    __shared__ int base_sh;
    if (tid == 0) {
        if (blockIdx.x == 0) {
            atomicExch(&g_state[0], ((ull)(unsigned)total << 2) | 2ull);
            base_sh = 0;
        } else {
            atomicExch(&g_state[blockIdx.x], ((ull)(unsigned)total << 2) | 1ull);
            int base = 0;
            for (int b = blockIdx.x - 1; b >= 0; b--) {
                ull st;
                do { st = atomicAdd(&g_state[b], 0ull); } while ((st & 3ull) == 0ull);
                base += (int)(unsigned)(st >> 2);
                if ((st & 3ull) == 2ull) break;
            }
            atomicExch(&g_state[blockIdx.x], ((ull)(unsigned)(base + total) << 2) | 2ull);
            base_sh = base;
        }
    }
    __syncthreads();
    const int base = base_sh;

    if (i < n) {
        int di = g_degi[i];
        int inclusive = base + incl;
        int excl = inclusive - di;
        g_rowptr[i] = excl;
        g_cursor[i] = excl;
        g_dinv[i] = (di > 0) ? rsqrtf((float)di) : 0.0f;
        if (i == n - 1) g_rowptr[n] = inclusive;
    }
}

// ---- fill CSR + quantize x + split W + init out (block-range split) ----
__global__ void k_fillquant(const int* __restrict__ src, const int* __restrict__ dst,
                            const float* __restrict__ x, __half* __restrict__ x16,
                            const float* __restrict__ W0, const float* __restrict__ W1,
                            const float* __restrict__ bout, float* __restrict__ out,
                            int E, int n4, int G, int EB, int QB) {
    if ((int)blockIdx.x < EB) {
        int e = blockIdx.x * 256 + threadIdx.x;
        if (e >= E) return;
        int s = src[e], d = dst[e];
        int pos = atomicAdd(&g_cursor[d], 1);
        int2 ed;
        ed.x = s;
        ed.y = __float_as_int(g_dinv[s] * g_dinv[d]);
        g_edge[pos] = ed;
    } else if ((int)blockIdx.x < EB + QB) {
        int i = (blockIdx.x - EB) * 256 + threadIdx.x;
        if (i >= n4) return;
        float4 v = ((const float4*)x)[i];
        __half2 a = __floats2half2_rn(v.x, v.y);
        __half2 b = __floats2half2_rn(v.z, v.w);
        uint2 p;
        p.x = *(unsigned*)&a;
        p.y = *(unsigned*)&b;
        ((uint2*)x16)[i] = p;
    } else if ((int)blockIdx.x == gridDim.x - 1) {
        int i = threadIdx.x;
        if (i < G) out[i] = bout[0];
    } else {
        int c = (blockIdx.x - EB - QB) * 256 + threadIdx.x;
        if (c >= 8192) return;
        int f = c * 4;
        float4 wv = (f < 16384) ? *(const float4*)&W0[f] : *(const float4*)&W1[f - 16384];
        __half hx = __float2half_rn(wv.x), hy = __float2half_rn(wv.y);
        __half hz = __float2half_rn(wv.z), hw = __float2half_rn(wv.w);
        __half lx = __float2half_rn(wv.x - __half2float(hx));
        __half ly = __float2half_rn(wv.y - __half2float(hy));
        __half lz = __float2half_rn(wv.z - __half2float(hz));
        __half lw = __float2half_rn(wv.w - __half2float(hw));
        __half2 h01 = __halves2half2(hx, hy), h23 = __halves2half2(hz, hw);
        __half2 l01 = __halves2half2(lx, ly), l23 = __halves2half2(lz, lw);
        uint2 ph, pl;
        ph.x = *(unsigned*)&h01;  ph.y = *(unsigned*)&h23;
        pl.x = *(unsigned*)&l01;  pl.y = *(unsigned*)&l23;
        *(uint2*)&g_whi[f] = ph;
        *(uint2*)&g_wlo[f] = pl;
    }
}

// ---------------- ldmatrix / mma helpers ----------------
#define LDSM_X4(r0, r1, r2, r3, a) \
    asm volatile("ldmatrix.sync.aligned.m8n8.x4.shared.b16 {%0,%1,%2,%3}, [%4];" \
                 : "=r"(r0), "=r"(r1), "=r"(r2), "=r"(r3) : "r"(a))
#define LDSM_X4_T(r0, r1, r2, r3, a) \
    asm volatile("ldmatrix.sync.aligned.m8n8.x4.trans.shared.b16 {%0,%1,%2,%3}, [%4];" \
                 : "=r"(r0), "=r"(r1), "=r"(r2), "=r"(r3) : "r"(a))
#define HMMA(d0, d1, d2, d3, a0, a1, a2, a3, b0, b1) \
    asm volatile("mma.sync.aligned.m16n8k16.row.col.f32.f16.f16.f32 " \
                 "{%0,%1,%2,%3}, {%4,%5,%6,%7}, {%8,%9}, {%0,%1,%2,%3};" \
                 : "+f"(d0), "+f"(d1), "+f"(d2), "+f"(d3) \
                 : "r"(a0), "r"(a1), "r"(a2), "r"(a3), "r"(b0), "r"(b1))

#define HS_STRIDE 72

#define GEMM_PASS() \
    do { \
        unsigned aAddr = (unsigned)__cvta_generic_to_shared(&Hs[(m0 + lr) * HS_STRIDE + lc]); \
        unsigned bh0 = (unsigned)__cvta_generic_to_shared(&Whi[lr * HS_STRIDE + n0w + lc]); \
        unsigned bh1 = (unsigned)__cvta_generic_to_shared(&Whi[lr * HS_STRIDE + n0w + 16 + lc]); \
        unsigned bl0 = (unsigned)__cvta_generic_to_shared(&Wlo[lr * HS_STRIDE + n0w + lc]); \
        unsigned bl1 = (unsigned)__cvta_generic_to_shared(&Wlo[lr * HS_STRIDE + n0w + 16 + lc]); \
        _Pragma("unroll") \
        for (int ks = 0; ks < 4; ks++) { \
            unsigned a0, a1, a2, a3; \
            LDSM_X4(a0, a1, a2, a3, aAddr + ks * 32); \
            unsigned h0, h1, h2, h3, h4, h5, h6, h7; \
            LDSM_X4_T(h0, h1, h2, h3, bh0 + ks * kstepB); \
            LDSM_X4_T(h4, h5, h6, h7, bh1 + ks * kstepB); \
            unsigned l0, l1, l2, l3, l4, l5, l6, l7; \
            LDSM_X4_T(l0, l1, l2, l3, bl0 + ks * kstepB); \
            LDSM_X4_T(l4, l5, l6, l7, bl1 + ks * kstepB); \
            HMMA(d0[0], d1[0], d2[0], d3[0], a0, a1, a2, a3, h0, h1); \
            HMMA(d0[1], d1[1], d2[1], d3[1], a0, a1, a2, a3, h2, h3); \
            HMMA(d0[2], d1[2], d2[2], d3[2], a0, a1, a2, a3, h4, h5); \
            HMMA(d0[3], d1[3], d2[3], d3[3], a0, a1, a2, a3, h6, h7); \
            HMMA(d0[0], d1[0], d2[0], d3[0], a0, a1, a2, a3, l0, l1); \
            HMMA(d0[1], d1[1], d2[1], d3[1], a0, a1, a2, a3, l2, l3); \
            HMMA(d0[2], d1[2], d2[2], d3[2], a0, a1, a2, a3, l4, l5); \
            HMMA(d0[3], d1[3], d2[3], d3[3], a0, a1, a2, a3, l6, l7); \
        } \
    } while (0)

// ---------------- stage kernel: HMMA GEMM blocks + hop blocks ----------
// GMODE 0: acc = h@W + bias        GMODE 1: acc += h@W
// GMODE 2: y16 = prelu(acc + h@W)  GMODE 3: pool(prelu(acc + h@W)) -> out
template <int GMODE, bool HOP>
__global__ void __launch_bounds__(256, 6) k_stage(const __half* __restrict__ hin,
                                                  const __half* __restrict__ whi,
                                                  const __half* __restrict__ wlo,
                                                  float* __restrict__ acc,
                                                  const float* __restrict__ bias,
                                                  const float* __restrict__ alpha,
                                                  __half* __restrict__ hopout,
                                                  __half* __restrict__ y16,
                                                  const int* __restrict__ bids,
                                                  const float* __restrict__ Wout,
                                                  float* __restrict__ out,
                                                  int N, int GB) {
    __shared__ __half Hs[64 * HS_STRIDE];
    __shared__ __half Whi[64 * HS_STRIDE];
    __shared__ __half Wlo[64 * HS_STRIDE];

    const int tid = threadIdx.x;

    if (HOP && (int)blockIdx.x >= GB) {
        const int lane = tid & 31;
        const int node = (blockIdx.x - GB) * 8 + (tid >> 5);
        if (node >= N) return;
        int p = g_rowptr[node];
        const int end = g_rowptr[node + 1];
        float ax = 0.f, ay = 0.f;
        if (p < end && (p & 1)) {  // align to int4
            int2 e = g_edge[p];
            float wv = __int_as_float(e.y);
            float2 v = __half22float2(__ldg((const __half2*)&hin[(size_t)e.x * D + lane * 2]));
            ax += wv * v.x;  ay += wv * v.y;
            p++;
        }
        for (; p + 8 <= end; p += 8) {  // 8-edge unroll: MLP 8
            int4 a = *(const int4*)&g_edge[p];
            int4 b = *(const int4*)&g_edge[p + 2];
            int4 c = *(const int4*)&g_edge[p + 4];
            int4 dd = *(const int4*)&g_edge[p + 6];
            float2 v0 = __half22float2(__ldg((const __half2*)&hin[(size_t)a.x * D + lane * 2]));
            float2 v1 = __half22float2(__ldg((const __half2*)&hin[(size_t)a.z * D + lane * 2]));
            float2 v2 = __half22float2(__ldg((const __half2*)&hin[(size_t)b.x * D + lane * 2]));
            float2 v3 = __half22float2(__ldg((const __half2*)&hin[(size_t)b.z * D + lane * 2]));
            float2 v4 = __half22float2(__ldg((const __half2*)&hin[(size_t)c.x * D + lane * 2]));
            float2 v5 = __half22float2(__ldg((const __half2*)&hin[(size_t)c.z * D + lane * 2]));
            float2 v6 = __half22float2(__ldg((const __half2*)&hin[(size_t)dd.x * D + lane * 2]));
            float2 v7 = __half22float2(__ldg((const __half2*)&hin[(size_t)dd.z * D + lane * 2]));
            float w0 = __int_as_float(a.y),  w1 = __int_as_float(a.w);
            float w2 = __int_as_float(b.y),  w3 = __int_as_float(b.w);
            float w4 = __int_as_float(c.y),  w5 = __int_as_float(c.w);
            float w6 = __int_as_float(dd.y), w7 = __int_as_float(dd.w);
            ax += w0 * v0.x;  ay += w0 * v0.y;
            ax += w1 * v1.x;  ay += w1 * v1.y;
            ax += w2 * v2.x;  ay += w2 * v2.y;
            ax += w3 * v3.x;  ay += w3 * v3.y;
            ax += w4 * v4.x;  ay += w4 * v4.y;
            ax += w5 * v5.x;  ay += w5 * v5.y;
            ax += w6 * v6.x;  ay += w6 * v6.y;
            ax += w7 * v7.x;  ay += w7 * v7.y;
        }
        for (; p + 2 <= end; p += 2) {
            int4 a = *(const int4*)&g_edge[p];
            float w0 = __int_as_float(a.y), w1 = __int_as_float(a.w);
            float2 v0 = __half22float2(__ldg((const __half2*)&hin[(size_t)a.x * D + lane * 2]));
            float2 v1 = __half22float2(__ldg((const __half2*)&hin[(size_t)a.z * D + lane * 2]));
            ax += w0 * v0.x;  ay += w0 * v0.y;
            ax += w1 * v1.x;  ay += w1 * v1.y;
        }
        if (p < end) {
            int2 e = g_edge[p];
            float wv = __int_as_float(e.y);
            float2 v = __half22float2(__ldg((const __half2*)&hin[(size_t)e.x * D + lane * 2]));
            ax += wv * v.x;  ay += wv * v.y;
        }
        *(__half2*)&hopout[(size_t)node * D + lane * 2] = __floats2half2_rn(ax, ay);
        return;
    }

    // ================= HMMA GEMM block =================
    const int n0blk = blockIdx.x * 64;

#pragma unroll
    for (int i = 0; i < 2; i++) {
        int idx = tid + i * 256;
        int r = idx >> 3;
        int c8 = (idx & 7) * 8;
        int4 v = make_int4(0, 0, 0, 0);
        if (n0blk + r < N) v = *(const int4*)&hin[(size_t)(n0blk + r) * D + c8];
        *(int4*)&Hs[r * HS_STRIDE + c8] = v;
        *(int4*)&Whi[r * HS_STRIDE + c8] = *(const int4*)&whi[r * 64 + c8];
        *(int4*)&Wlo[r * HS_STRIDE + c8] = *(const int4*)&wlo[r * 64 + c8];
    }
    __syncthreads();

    const int w = tid >> 5;
    const int lane = tid & 31;
    const int m0 = (w & 3) * 16;
    const int n0w = (w >> 2) * 32;
    const int lr = lane & 15;
    const int lc = (lane >> 4) * 8;
    const unsigned kstepB = 16 * HS_STRIDE * 2;

    float d0[4], d1[4], d2[4], d3[4];
#pragma unroll
    for (int j = 0; j < 4; j++) { d0[j] = d1[j] = d2[j] = d3[j] = 0.f; }

    GEMM_PASS();

    // ---- epilogue ----
    const int grp = lane >> 2;
    const int qt = lane & 3;
    const int row0 = n0blk + m0 + grp;
    const int row1 = row0 + 8;
    float a0s = 0.f;
    if (GMODE >= 2) a0s = alpha[0];
    float part0 = 0.f, part1 = 0.f;

#pragma unroll
    for (int j = 0; j < 4; j++) {
        const int cb = n0w + j * 8 + qt * 2;
        float2 bvj = make_float2(0.f, 0.f);
        if (GMODE == 0) bvj = *(const float2*)&bias[cb];
        float2 wvj = make_float2(0.f, 0.f);
        if (GMODE == 3) wvj = *(const float2*)&Wout[cb];

        if (GMODE == 0) {
            if (row0 < N)
                *(float2*)&acc[(size_t)row0 * D + cb] = make_float2(d0[j] + bvj.x, d1[j] + bvj.y);
            if (row1 < N)
                *(float2*)&acc[(size_t)row1 * D + cb] = make_float2(d2[j] + bvj.x, d3[j] + bvj.y);
        } else if (GMODE == 1) {
            if (row0 < N) {
                float* ap = &acc[(size_t)row0 * D + cb];
                float2 o = *(const float2*)ap;
                o.x += d0[j]; o.y += d1[j];
                *(float2*)ap = o;
            }
            if (row1 < N) {
                float* ap = &acc[(size_t)row1 * D + cb];
                float2 o = *(const float2*)ap;
                o.x += d2[j]; o.y += d3[j];
                *(float2*)ap = o;
            }
        } else {
            float2 o0 = make_float2(0.f, 0.f), o1 = make_float2(0.f, 0.f);
            if (row0 < N) {
                o0 = *(const float2*)&acc[(size_t)row0 * D + cb];
                o0.x += d0[j]; o0.y += d1[j];
                o0.x = (o0.x >= 0.f) ? o0.x : a0s * o0.x;
                o0.y = (o0.y >= 0.f) ? o0.y : a0s * o0.y;
            }
            if (row1 < N) {
                o1 = *(const float2*)&acc[(size_t)row1 * D + cb];
                o1.x += d2[j]; o1.y += d3[j];
                o1.x = (o1.x >= 0.f) ? o1.x : a0s * o1.x;
                o1.y = (o1.y >= 0.f) ? o1.y : a0s * o1.y;
            }
            if (GMODE == 2) {
                if (row0 < N) *(__half2*)&y16[(size_t)row0 * D + cb] = __floats2half2_rn(o0.x, o0.y);
                if (row1 < N) *(__half2*)&y16[(size_t)row1 * D + cb] = __floats2half2_rn(o1.x, o1.y);
            } else {
                if (row0 < N) part0 += o0.x * wvj.x + o0.y * wvj.y;
                if (row1 < N) part1 += o1.x * wvj.x + o1.y * wvj.y;
            }
        }
    }

    if (GMODE == 3) {
        part0 += __shfl_xor_sync(0xffffffffu, part0, 1);
        part0 += __shfl_xor_sync(0xffffffffu, part0, 2);
        part1 += __shfl_xor_sync(0xffffffffu, part1, 1);
        part1 += __shfl_xor_sync(0xffffffffu, part1, 2);
        if (qt == 0) {
            if (row0 < N) atomicAdd(&out[bids[row0]], part0);
            if (row1 < N) atomicAdd(&out[bids[row1]], part1);
        }
    }
}

// ---------------- launch ----------------
extern "C" void kernel_launch(void* const* d_in, const int* in_sizes, int n_in,
                              void* d_out, int out_size) {
    const float* x    = (const float*)d_in[0];
    const int*   ei   = (const int*)d_in[1];
    const int*   bids = (const int*)d_in[2];
    const float* W0   = (const float*)d_in[3];
    const float* b0   = (const float*)d_in[4];
    const float* W1   = (const float*)d_in[5];
    const float* b1   = (const float*)d_in[6];
    const float* al0  = (const float*)d_in[7];
    const float* al1  = (const float*)d_in[8];
    const float* Wout = (const float*)d_in[9];
    const float* bout = (const float*)d_in[10];
    float* out = (float*)d_out;

    const int N = in_sizes[0] / D;
    const int E = in_sizes[1] / 2;
    const int* src = ei;
    const int* dst = ei + E;

    void* p_degi;
    __half *x16, *hA, *hB, *y16, *whi, *wlo;
    float* accp;
    cudaGetSymbolAddress(&p_degi, g_degi);
    cudaGetSymbolAddress((void**)&x16, g_x16);
    cudaGetSymbolAddress((void**)&hA, g_hA16);
    cudaGetSymbolAddress((void**)&hB, g_hB16);
    cudaGetSymbolAddress((void**)&y16, g_y16);
    cudaGetSymbolAddress((void**)&whi, g_whi);
    cudaGetSymbolAddress((void**)&wlo, g_wlo);
    cudaGetSymbolAddress((void**)&accp, g_acc);

    cudaMemsetAsync(p_degi, 0, (size_t)N * sizeof(int));

    const int EB = (E + 255) / 256;
    const int QB = (N * 16 + 255) / 256;
    const int WB = 32;
    k_deg<<<EB, 256>>>(dst, E);
    k_scan<<<(N + 1023) / 1024, 1024>>>(N);
    k_fillquant<<<EB + QB + WB + 1, 256>>>(src, dst, x, x16, W0, W1, bout, out,
                                           E, N * 16, out_size, EB, QB);

    const int GB = (N + 63) / 64;
    const int HB = (N + 7) / 8;
    const int FULL = GB + HB;

    // ---- layer 0 ----
    k_stage<0, true ><<<FULL, 256>>>(x16, whi,         wlo,         accp, b0,      nullptr, hA,  nullptr, nullptr, nullptr, nullptr, N, GB);
    k_stage<1, true ><<<FULL, 256>>>(hA,  whi + 4096,  wlo + 4096,  accp, nullptr, nullptr, hB,  nullptr, nullptr, nullptr, nullptr, N, GB);
    k_stage<1, true ><<<FULL, 256>>>(hB,  whi + 8192,  wlo + 8192,  accp, nullptr, nullptr, hA,  nullptr, nullptr, nullptr, nullptr, N, GB);
    k_stage<2, false><<<GB,   256>>>(hA,  whi + 12288, wlo + 12288, accp, nullptr, al0,     nullptr, y16, nullptr, nullptr, nullptr, N, GB);

    // ---- layer 1 ----
    k_stage<0, true ><<<FULL, 256>>>(y16, whi + 16384, wlo + 16384, accp, b1,      nullptr, hB,  nullptr, nullptr, nullptr, nullptr, N, GB);
    k_stage<1, true ><<<FULL, 256>>>(hB,  whi + 20480, wlo + 20480, accp, nullptr, nullptr, hA,  nullptr, nullptr, nullptr, nullptr, N, GB);
    k_stage<1, true ><<<FULL, 256>>>(hA,  whi + 24576, wlo + 24576, accp, nullptr, nullptr, hB,  nullptr, nullptr, nullptr, nullptr, N, GB);
    k_stage<3, false><<<GB,   256>>>(hB,  whi + 28672, wlo + 28672, accp, nullptr, al1,     nullptr, nullptr, bids, Wout, out, N, GB);
}

// round 12
// speedup vs baseline: 1.1053x; 1.0530x over previous
#include <cuda_runtime.h>
#include <cuda_fp16.h>

#define D 64
#define NMAX 50048
#define EMAX 800000

typedef unsigned long long ull;

// ---------------- scratch (no allocation allowed) ----------------
__device__ int    g_degi[NMAX];
__device__ int    g_cursor[NMAX];
__device__ float  g_dinv[NMAX];
__device__ int    g_rowptr[NMAX + 1];
__device__ ull    g_state[64];           // lookback scan state (value<<2 | status)
__device__ int2   g_edge[EMAX + 8];      // {src, wn bits}; padded
__device__ __half g_x16[(size_t)NMAX * D];
__device__ __half g_hA16[(size_t)NMAX * D];
__device__ __half g_hB16[(size_t)NMAX * D];
__device__ __half g_y16[(size_t)NMAX * D];
__device__ float  g_acc[(size_t)NMAX * D];
__device__ __half g_whi[8 * 4096];       // W hi fp16 planes (8 matrices)
__device__ __half g_wlo[8 * 4096];       // W lo fp16 planes

// ---------------- degree count (also resets scan state) ----------------
__global__ void k_deg(const int* __restrict__ dst, int E) {
    int e = blockIdx.x * blockDim.x + threadIdx.x;
    if (blockIdx.x == 0 && threadIdx.x < 64) g_state[threadIdx.x] = 0ull;
    if (e < E) atomicAdd(&g_degi[dst[e]], 1);
}

// ---------------- single-pass decoupled-lookback scan + dinv + cursor ----
__global__ void __launch_bounds__(1024) k_scan(int n) {
    const int tid = threadIdx.x;
    const int lane = tid & 31;
    const int w = tid >> 5;
    const int i = blockIdx.x * 1024 + tid;
    int v = (i < n) ? g_degi[i] : 0;

    int s = v;
#pragma unroll
    for (int off = 1; off < 32; off <<= 1) {
        int t = __shfl_up_sync(0xffffffffu, s, off);
        if (lane >= off) s += t;
    }
    __shared__ int wsum[32];
    if (lane == 31) wsum[w] = s;
    __syncthreads();
    if (w == 0) {
        int t = wsum[lane];
#pragma unroll
        for (int off = 1; off < 32; off <<= 1) {
            int u = __shfl_up_sync(0xffffffffu, t, off);
            if (lane >= off) t += u;
        }
        wsum[lane] = t;
    }
    __syncthreads();
    const int incl = s + (w > 0 ? wsum[w - 1] : 0);
    const int total = wsum[31];

    __shared__ int base_sh;
    if (tid == 0) {
        if (blockIdx.x == 0) {
            atomicExch(&g_state[0], ((ull)(unsigned)total << 2) | 2ull);
            base_sh = 0;
        } else {
            atomicExch(&g_state[blockIdx.x], ((ull)(unsigned)total << 2) | 1ull);
            int base = 0;
            for (int b = blockIdx.x - 1; b >= 0; b--) {
                ull st;
                do { st = atomicAdd(&g_state[b], 0ull); } while ((st & 3ull) == 0ull);
                base += (int)(unsigned)(st >> 2);
                if ((st & 3ull) == 2ull) break;
            }
            atomicExch(&g_state[blockIdx.x], ((ull)(unsigned)(base + total) << 2) | 2ull);
            base_sh = base;
        }
    }
    __syncthreads();
    const int base = base_sh;

    if (i < n) {
        int di = g_degi[i];
        int inclusive = base + incl;
        int excl = inclusive - di;
        g_rowptr[i] = excl;
        g_cursor[i] = excl;
        g_dinv[i] = (di > 0) ? rsqrtf((float)di) : 0.0f;
        if (i == n - 1) g_rowptr[n] = inclusive;
    }
}

// fill CSR + quantize x + split W + zero degi + init out (block-range split)
__global__ void k_fillquant(const int* __restrict__ src, const int* __restrict__ dst,
                            const float* __restrict__ x, __half* __restrict__ x16,
                            const float* __restrict__ W0, const float* __restrict__ W1,
                            const float* __restrict__ bout, float* __restrict__ out,
                            int E, int n4, int G, int EB, int QB, int WB) {
    if ((int)blockIdx.x < EB) {
        int e = blockIdx.x * 256 + threadIdx.x;
        if (e >= E) return;
        int s = src[e], d = dst[e];
        int pos = atomicAdd(&g_cursor[d], 1);
        int2 ed;
        ed.x = s;
        ed.y = __float_as_int(g_dinv[s] * g_dinv[d]);
        g_edge[pos] = ed;
    } else if ((int)blockIdx.x < EB + QB) {
        int i = (blockIdx.x - EB) * 256 + threadIdx.x;
        if (i >= n4) return;
        float4 v = ((const float4*)x)[i];
        __half2 a = __floats2half2_rn(v.x, v.y);
        __half2 b = __floats2half2_rn(v.z, v.w);
        uint2 p;
        p.x = *(unsigned*)&a;
        p.y = *(unsigned*)&b;
        ((uint2*)x16)[i] = p;
    } else if ((int)blockIdx.x < EB + QB + WB) {
        int c = (blockIdx.x - EB - QB) * 256 + threadIdx.x;
        if (c >= 8192) return;
        int f = c * 4;
        float4 wv = (f < 16384) ? *(const float4*)&W0[f] : *(const float4*)&W1[f - 16384];
        __half hx = __float2half_rn(wv.x), hy = __float2half_rn(wv.y);
        __half hz = __float2half_rn(wv.z), hw = __float2half_rn(wv.w);
        __half lx = __float2half_rn(wv.x - __half2float(hx));
        __half ly = __float2half_rn(wv.y - __half2float(hy));
        __half lz = __float2half_rn(wv.z - __half2float(hz));
        __half lw = __float2half_rn(wv.w - __half2float(hw));
        __half2 h01 = __halves2half2(hx, hy), h23 = __halves2half2(hz, hw);
        __half2 l01 = __halves2half2(lx, ly), l23 = __halves2half2(lz, lw);
        uint2 ph, pl;
        ph.x = *(unsigned*)&h01;  ph.y = *(unsigned*)&h23;
        pl.x = *(unsigned*)&l01;  pl.y = *(unsigned*)&l23;
        *(uint2*)&g_whi[f] = ph;
        *(uint2*)&g_wlo[f] = pl;
    } else if ((int)blockIdx.x == gridDim.x - 1) {
        int i = threadIdx.x;
        if (i < G) out[i] = bout[0];
    } else {
        // zero g_degi for next launch (degi already consumed by k_scan)
        int i = (blockIdx.x - EB - QB - WB) * 256 + threadIdx.x;
        if (i < NMAX / 4) ((int4*)g_degi)[i] = make_int4(0, 0, 0, 0);
    }
}

// ---------------- ldmatrix / mma helpers ----------------
#define LDSM_X4(r0, r1, r2, r3, a) \
    asm volatile("ldmatrix.sync.aligned.m8n8.x4.shared.b16 {%0,%1,%2,%3}, [%4];" \
                 : "=r"(r0), "=r"(r1), "=r"(r2), "=r"(r3) : "r"(a))
#define LDSM_X4_T(r0, r1, r2, r3, a) \
    asm volatile("ldmatrix.sync.aligned.m8n8.x4.trans.shared.b16 {%0,%1,%2,%3}, [%4];" \
                 : "=r"(r0), "=r"(r1), "=r"(r2), "=r"(r3) : "r"(a))
#define HMMA(d0, d1, d2, d3, a0, a1, a2, a3, b0, b1) \
    asm volatile("mma.sync.aligned.m16n8k16.row.col.f32.f16.f16.f32 " \
                 "{%0,%1,%2,%3}, {%4,%5,%6,%7}, {%8,%9}, {%0,%1,%2,%3};" \
                 : "+f"(d0), "+f"(d1), "+f"(d2), "+f"(d3) \
                 : "r"(a0), "r"(a1), "r"(a2), "r"(a3), "r"(b0), "r"(b1))

#define HS_STRIDE 72
#define SM_HALFS  (64 * HS_STRIDE)
#define EM_CAP    3448                 // int2 capacity of the 27.6KB smem pool

#define GEMM_PASS() \
    do { \
        unsigned aAddr = (unsigned)__cvta_generic_to_shared(&Hs[(m0 + lr) * HS_STRIDE + lc]); \
        unsigned bh0 = (unsigned)__cvta_generic_to_shared(&Whi[lr * HS_STRIDE + n0w + lc]); \
        unsigned bh1 = (unsigned)__cvta_generic_to_shared(&Whi[lr * HS_STRIDE + n0w + 16 + lc]); \
        unsigned bl0 = (unsigned)__cvta_generic_to_shared(&Wlo[lr * HS_STRIDE + n0w + lc]); \
        unsigned bl1 = (unsigned)__cvta_generic_to_shared(&Wlo[lr * HS_STRIDE + n0w + 16 + lc]); \
        _Pragma("unroll") \
        for (int ks = 0; ks < 4; ks++) { \
            unsigned a0, a1, a2, a3; \
            LDSM_X4(a0, a1, a2, a3, aAddr + ks * 32); \
            unsigned h0, h1, h2, h3, h4, h5, h6, h7; \
            LDSM_X4_T(h0, h1, h2, h3, bh0 + ks * kstepB); \
            LDSM_X4_T(h4, h5, h6, h7, bh1 + ks * kstepB); \
            unsigned l0, l1, l2, l3, l4, l5, l6, l7; \
            LDSM_X4_T(l0, l1, l2, l3, bl0 + ks * kstepB); \
            LDSM_X4_T(l4, l5, l6, l7, bl1 + ks * kstepB); \
            HMMA(d0[0], d1[0], d2[0], d3[0], a0, a1, a2, a3, h0, h1); \
            HMMA(d0[1], d1[1], d2[1], d3[1], a0, a1, a2, a3, h2, h3); \
            HMMA(d0[2], d1[2], d2[2], d3[2], a0, a1, a2, a3, h4, h5); \
            HMMA(d0[3], d1[3], d2[3], d3[3], a0, a1, a2, a3, h6, h7); \
            HMMA(d0[0], d1[0], d2[0], d3[0], a0, a1, a2, a3, l0, l1); \
            HMMA(d0[1], d1[1], d2[1], d3[1], a0, a1, a2, a3, l2, l3); \
            HMMA(d0[2], d1[2], d2[2], d3[2], a0, a1, a2, a3, l4, l5); \
            HMMA(d0[3], d1[3], d2[3], d3[3], a0, a1, a2, a3, l6, l7); \
        } \
    } while (0)

// 8-edge FMA batch with metadata from EM (smem int2*) at indices [p, p+8)
#define HOP8_SMEM(P)                                                              \
    do {                                                                          \
        int4 a  = *(const int4*)&em[(P)];                                         \
        int4 b  = *(const int4*)&em[(P) + 2];                                     \
        int4 c  = *(const int4*)&em[(P) + 4];                                     \
        int4 dd = *(const int4*)&em[(P) + 6];                                     \
        float2 v0 = __half22float2(__ldg(hbase + (size_t)a.x * 32));              \
        float2 v1 = __half22float2(__ldg(hbase + (size_t)a.z * 32));              \
        float2 v2 = __half22float2(__ldg(hbase + (size_t)b.x * 32));              \
        float2 v3 = __half22float2(__ldg(hbase + (size_t)b.z * 32));              \
        float2 v4 = __half22float2(__ldg(hbase + (size_t)c.x * 32));              \
        float2 v5 = __half22float2(__ldg(hbase + (size_t)c.z * 32));              \
        float2 v6 = __half22float2(__ldg(hbase + (size_t)dd.x * 32));             \
        float2 v7 = __half22float2(__ldg(hbase + (size_t)dd.z * 32));             \
        float w0 = __int_as_float(a.y),  w1 = __int_as_float(a.w);                \
        float w2 = __int_as_float(b.y),  w3 = __int_as_float(b.w);                \
        float w4 = __int_as_float(c.y),  w5 = __int_as_float(c.w);                \
        float w6 = __int_as_float(dd.y), w7 = __int_as_float(dd.w);               \
        ax += w0 * v0.x;  ay += w0 * v0.y;                                        \
        ax += w1 * v1.x;  ay += w1 * v1.y;                                        \
        ax += w2 * v2.x;  ay += w2 * v2.y;                                        \
        ax += w3 * v3.x;  ay += w3 * v3.y;                                        \
        ax += w4 * v4.x;  ay += w4 * v4.y;                                        \
        ax += w5 * v5.x;  ay += w5 * v5.y;                                        \
        ax += w6 * v6.x;  ay += w6 * v6.y;                                        \
        ax += w7 * v7.x;  ay += w7 * v7.y;                                        \
    } while (0)

// ---------------- stage kernel: HMMA GEMM blocks + hop blocks ----------
// GMODE 0: acc = h@W + bias        GMODE 1: acc += h@W
// GMODE 2: y16 = prelu(acc + h@W)  GMODE 3: pool(prelu(acc + h@W)) -> out
template <int GMODE, bool HOP>
__global__ void __launch_bounds__(256, 6) k_stage(const __half* __restrict__ hin,
                                                  const __half* __restrict__ whi,
                                                  const __half* __restrict__ wlo,
                                                  float* __restrict__ acc,
                                                  const float* __restrict__ bias,
                                                  const float* __restrict__ alpha,
                                                  __half* __restrict__ hopout,
                                                  __half* __restrict__ y16,
                                                  const int* __restrict__ bids,
                                                  const float* __restrict__ Wout,
                                                  float* __restrict__ out,
                                                  int N, int GB) {
    __shared__ __align__(16) __half smem_h[3 * SM_HALFS];
    __shared__ int rp[9];
    __half* Hs  = smem_h;
    __half* Whi = smem_h + SM_HALFS;
    __half* Wlo = smem_h + 2 * SM_HALFS;

    const int tid = threadIdx.x;

    if (HOP && (int)blockIdx.x >= GB) {
        // ---- hop: 8 nodes/block; edge metadata staged through smem ----
        const int lane = tid & 31;
        const int w = tid >> 5;
        const int nb0 = (blockIdx.x - GB) * 8;
        if (tid < 9) rp[tid] = g_rowptr[min(nb0 + tid, N)];
        __syncthreads();
        const int e0 = rp[0];
        const int cnt = rp[8] - e0;
        const __half2* __restrict__ hbase = (const __half2*)hin + lane;
        const int node = nb0 + w;
        float ax = 0.f, ay = 0.f;

        if (cnt <= EM_CAP) {
            int2* em = (int2*)smem_h;
            for (int i = tid; i < cnt; i += 256) em[i] = g_edge[e0 + i];
            __syncthreads();
            int p = rp[w] - e0;
            const int end = rp[w + 1] - e0;
            if (p < end && (p & 1)) {
                int2 e = em[p];
                float wv = __int_as_float(e.y);
                float2 v = __half22float2(__ldg(hbase + (size_t)e.x * 32));
                ax += wv * v.x;  ay += wv * v.y;
                p++;
            }
            for (; p + 8 <= end; p += 8) HOP8_SMEM(p);
            for (; p + 2 <= end; p += 2) {
                int4 a = *(const int4*)&em[p];
                float w0 = __int_as_float(a.y), w1 = __int_as_float(a.w);
                float2 v0 = __half22float2(__ldg(hbase + (size_t)a.x * 32));
                float2 v1 = __half22float2(__ldg(hbase + (size_t)a.z * 32));
                ax += w0 * v0.x;  ay += w0 * v0.y;
                ax += w1 * v1.x;  ay += w1 * v1.y;
            }
            if (p < end) {
                int2 e = em[p];
                float wv = __int_as_float(e.y);
                float2 v = __half22float2(__ldg(hbase + (size_t)e.x * 32));
                ax += wv * v.x;  ay += wv * v.y;
            }
        } else {
            // fallback: direct gmem metadata (giant range, never expected)
            int p = rp[w];
            const int end = rp[w + 1];
            for (; p < end; p++) {
                int2 e = g_edge[p];
                float wv = __int_as_float(e.y);
                float2 v = __half22float2(__ldg(hbase + (size_t)e.x * 32));
                ax += wv * v.x;  ay += wv * v.y;
            }
        }
        if (node < N)
            *(__half2*)&hopout[(size_t)node * D + lane * 2] = __floats2half2_rn(ax, ay);
        return;
    }

    // ================= HMMA GEMM block =================
    const int n0blk = blockIdx.x * 64;

#pragma unroll
    for (int i = 0; i < 2; i++) {
        int idx = tid + i * 256;
        int r = idx >> 3;
        int c8 = (idx & 7) * 8;
        int4 v = make_int4(0, 0, 0, 0);
        if (n0blk + r < N) v = *(const int4*)&hin[(size_t)(n0blk + r) * D + c8];
        *(int4*)&Hs[r * HS_STRIDE + c8] = v;
        *(int4*)&Whi[r * HS_STRIDE + c8] = *(const int4*)&whi[r * 64 + c8];
        *(int4*)&Wlo[r * HS_STRIDE + c8] = *(const int4*)&wlo[r * 64 + c8];
    }
    __syncthreads();

    const int w = tid >> 5;
    const int lane = tid & 31;
    const int m0 = (w & 3) * 16;
    const int n0w = (w >> 2) * 32;
    const int lr = lane & 15;
    const int lc = (lane >> 4) * 8;
    const unsigned kstepB = 16 * HS_STRIDE * 2;

    float d0[4], d1[4], d2[4], d3[4];
#pragma unroll
    for (int j = 0; j < 4; j++) { d0[j] = d1[j] = d2[j] = d3[j] = 0.f; }

    GEMM_PASS();

    // ---- epilogue ----
    const int grp = lane >> 2;
    const int qt = lane & 3;
    const int row0 = n0blk + m0 + grp;
    const int row1 = row0 + 8;
    float a0s = 0.f;
    if (GMODE >= 2) a0s = alpha[0];
    float part0 = 0.f, part1 = 0.f;

#pragma unroll
    for (int j = 0; j < 4; j++) {
        const int cb = n0w + j * 8 + qt * 2;
        float2 bvj = make_float2(0.f, 0.f);
        if (GMODE == 0) bvj = *(const float2*)&bias[cb];
        float2 wvj = make_float2(0.f, 0.f);
        if (GMODE == 3) wvj = *(const float2*)&Wout[cb];

        if (GMODE == 0) {
            if (row0 < N)
                *(float2*)&acc[(size_t)row0 * D + cb] = make_float2(d0[j] + bvj.x, d1[j] + bvj.y);
            if (row1 < N)
                *(float2*)&acc[(size_t)row1 * D + cb] = make_float2(d2[j] + bvj.x, d3[j] + bvj.y);
        } else if (GMODE == 1) {
            if (row0 < N) {
                float* ap = &acc[(size_t)row0 * D + cb];
                float2 o = *(const float2*)ap;
                o.x += d0[j]; o.y += d1[j];
                *(float2*)ap = o;
            }
            if (row1 < N) {
                float* ap = &acc[(size_t)row1 * D + cb];
                float2 o = *(const float2*)ap;
                o.x += d2[j]; o.y += d3[j];
                *(float2*)ap = o;
            }
        } else {
            float2 o0 = make_float2(0.f, 0.f), o1 = make_float2(0.f, 0.f);
            if (row0 < N) {
                o0 = *(const float2*)&acc[(size_t)row0 * D + cb];
                o0.x += d0[j]; o0.y += d1[j];
                o0.x = (o0.x >= 0.f) ? o0.x : a0s * o0.x;
                o0.y = (o0.y >= 0.f) ? o0.y : a0s * o0.y;
            }
            if (row1 < N) {
                o1 = *(const float2*)&acc[(size_t)row1 * D + cb];
                o1.x += d2[j]; o1.y += d3[j];
                o1.x = (o1.x >= 0.f) ? o1.x : a0s * o1.x;
                o1.y = (o1.y >= 0.f) ? o1.y : a0s * o1.y;
            }
            if (GMODE == 2) {
                if (row0 < N) *(__half2*)&y16[(size_t)row0 * D + cb] = __floats2half2_rn(o0.x, o0.y);
                if (row1 < N) *(__half2*)&y16[(size_t)row1 * D + cb] = __floats2half2_rn(o1.x, o1.y);
            } else {
                if (row0 < N) part0 += o0.x * wvj.x + o0.y * wvj.y;
                if (row1 < N) part1 += o1.x * wvj.x + o1.y * wvj.y;
            }
        }
    }

    if (GMODE == 3) {
        part0 += __shfl_xor_sync(0xffffffffu, part0, 1);
        part0 += __shfl_xor_sync(0xffffffffu, part0, 2);
        part1 += __shfl_xor_sync(0xffffffffu, part1, 1);
        part1 += __shfl_xor_sync(0xffffffffu, part1, 2);
        if (qt == 0) {
            if (row0 < N) atomicAdd(&out[bids[row0]], part0);
            if (row1 < N) atomicAdd(&out[bids[row1]], part1);
        }
    }
}

// ---------------- launch ----------------
extern "C" void kernel_launch(void* const* d_in, const int* in_sizes, int n_in,
                              void* d_out, int out_size) {
    const float* x    = (const float*)d_in[0];
    const int*   ei   = (const int*)d_in[1];
    const int*   bids = (const int*)d_in[2];
    const float* W0   = (const float*)d_in[3];
    const float* b0   = (const float*)d_in[4];
    const float* W1   = (const float*)d_in[5];
    const float* b1   = (const float*)d_in[6];
    const float* al0  = (const float*)d_in[7];
    const float* al1  = (const float*)d_in[8];
    const float* Wout = (const float*)d_in[9];
    const float* bout = (const float*)d_in[10];
    float* out = (float*)d_out;

    const int N = in_sizes[0] / D;
    const int E = in_sizes[1] / 2;
    const int* src = ei;
    const int* dst = ei + E;

    __half *x16, *hA, *hB, *y16, *whi, *wlo;
    float* accp;
    cudaGetSymbolAddress((void**)&x16, g_x16);
    cudaGetSymbolAddress((void**)&hA, g_hA16);
    cudaGetSymbolAddress((void**)&hB, g_hB16);
    cudaGetSymbolAddress((void**)&y16, g_y16);
    cudaGetSymbolAddress((void**)&whi, g_whi);
    cudaGetSymbolAddress((void**)&wlo, g_wlo);
    cudaGetSymbolAddress((void**)&accp, g_acc);

    const int EB = (E + 255) / 256;
    const int QB = (N * 16 + 255) / 256;
    const int WB = 32;
    const int ZB = (NMAX / 4 + 255) / 256;   // degi zeroing blocks
    k_deg<<<EB, 256>>>(dst, E);
    k_scan<<<(N + 1023) / 1024, 1024>>>(N);
    k_fillquant<<<EB + QB + WB + ZB + 1, 256>>>(src, dst, x, x16, W0, W1, bout, out,
                                                E, N * 16, out_size, EB, QB, WB);

    const int GB = (N + 63) / 64;
    const int HB = (N + 7) / 8;
    const int FULL = GB + HB;

    // ---- layer 0 ----
    k_stage<0, true ><<<FULL, 256>>>(x16, whi,         wlo,         accp, b0,      nullptr, hA,  nullptr, nullptr, nullptr, nullptr, N, GB);
    k_stage<1, true ><<<FULL, 256>>>(hA,  whi + 4096,  wlo + 4096,  accp, nullptr, nullptr, hB,  nullptr, nullptr, nullptr, nullptr, N, GB);
    k_stage<1, true ><<<FULL, 256>>>(hB,  whi + 8192,  wlo + 8192,  accp, nullptr, nullptr, hA,  nullptr, nullptr, nullptr, nullptr, N, GB);
    k_stage<2, false><<<GB,   256>>>(hA,  whi + 12288, wlo + 12288, accp, nullptr, al0,     nullptr, y16, nullptr, nullptr, nullptr, N, GB);

    // ---- layer 1 ----
    k_stage<0, true ><<<FULL, 256>>>(y16, whi + 16384, wlo + 16384, accp, b1,      nullptr, hB,  nullptr, nullptr, nullptr, nullptr, N, GB);
    k_stage<1, true ><<<FULL, 256>>>(hB,  whi + 20480, wlo + 20480, accp, nullptr, nullptr, hA,  nullptr, nullptr, nullptr, nullptr, N, GB);
    k_stage<1, true ><<<FULL, 256>>>(hA,  whi + 24576, wlo + 24576, accp, nullptr, nullptr, hB,  nullptr, nullptr, nullptr, nullptr, N, GB);
    k_stage<3, false><<<GB,   256>>>(hB,  whi + 28672, wlo + 28672, accp, nullptr, al1,     nullptr, nullptr, bids, Wout, out, N, GB);
}